// round 14
// baseline (speedup 1.0000x reference)
#include <cuda_runtime.h>
#include <cuda_bf16.h>
#include <cuda_fp16.h>
#include <stdint.h>
#include <math.h>

// Problem constants
#define BATCH 2
#define SEQ   2048
#define CDIM  1024
#define NHEAD 16
#define HDIM  64
#define MROWS (BATCH*SEQ)        // 4096
#define N_QKV (3*CDIM)           // 3072

// Scratch (device globals — allocation-free). Identical set to R12 (passed).
__device__ float g_qkv[(size_t)MROWS * N_QKV];              // q|k float (V region unused)
__device__ float g_vt[(size_t)BATCH * NHEAD * HDIM * SEQ];  // V^T float [B,NH,HD,T]
__device__ float g_y[(size_t)MROWS * CDIM];                 // attention out [B*T, C]

// ---------------------------------------------------------------------------
// helpers
// ---------------------------------------------------------------------------
__device__ __forceinline__ uint32_t f2tf32(float x) {
    uint32_t r;
    asm("cvt.rna.tf32.f32 %0, %1;" : "=r"(r) : "f"(x));
    return r;
}

__device__ __forceinline__ uint32_t h2u(float lo, float hi) {
    __half2 h = __floats2half2_rn(lo, hi);
    return *(uint32_t*)&h;
}

__device__ __forceinline__ void mma_tf32(float* c, const uint32_t* a, const uint32_t* b) {
    asm volatile("mma.sync.aligned.m16n8k8.row.col.f32.tf32.tf32.f32 "
        "{%0,%1,%2,%3}, {%4,%5,%6,%7}, {%8,%9}, {%0,%1,%2,%3};"
        : "+f"(c[0]), "+f"(c[1]), "+f"(c[2]), "+f"(c[3])
        : "r"(a[0]), "r"(a[1]), "r"(a[2]), "r"(a[3]), "r"(b[0]), "r"(b[1]));
}

__device__ __forceinline__ void mma_f16(float* c, const uint32_t* a, uint32_t b0, uint32_t b1) {
    asm volatile("mma.sync.aligned.m16n8k16.row.col.f32.f16.f16.f32 "
        "{%0,%1,%2,%3}, {%4,%5,%6,%7}, {%8,%9}, {%0,%1,%2,%3};"
        : "+f"(c[0]), "+f"(c[1]), "+f"(c[2]), "+f"(c[3])
        : "r"(a[0]), "r"(a[1]), "r"(a[2]), "r"(a[3]), "r"(b0), "r"(b1));
}

__device__ __forceinline__ void cp16(uint32_t smem_addr, const void* gmem) {
    asm volatile("cp.async.cg.shared.global [%0], [%1], 16;"
                 :: "r"(smem_addr), "l"(gmem));
}
__device__ __forceinline__ void cp_commit() {
    asm volatile("cp.async.commit_group;");
}
__device__ __forceinline__ void cp_wait1() {
    asm volatile("cp.async.wait_group 1;");
}
__device__ __forceinline__ void cp_wait0() {
    asm volatile("cp.async.wait_group 0;");
}

// ---------------------------------------------------------------------------
// TF32 cp.async double-buffered GEMM: C = A[M,K] @ B[K,N], fp32 row-major.
// 128x128x16 block tile, 256 threads (8 warps 2x4), warp tile 64x32,
// m16n8k8 tf32 (cvt.rna after fragment LDS — numerics identical to R8/R12).
// Raw fp32 tiles staged via cp.async, 2-stage ring:
//   As: [m 0..127][k 0..15] stride 20 floats (conflict-free frag loads)
//   Bs: [k 0..15][n 0..127] stride 132 floats (2-way on frag loads, as R8)
// Static smem: 2*(128*20 + 16*132)*4 = 37.4 KB.
// ---------------------------------------------------------------------------
#define TBM 128
#define TBN 128
#define TBK 16
#define AST 20
#define BST 132

template <bool V_TRANS>
__device__ __forceinline__ void tgemm_body(
    const float* __restrict__ A, const float* __restrict__ B,
    float* __restrict__ C, int N, int K)
{
    __shared__ float As[2][TBM * AST];   // 20.5 KB
    __shared__ float Bs[2][TBK * BST];   // 16.9 KB

    const int tid    = threadIdx.x;
    const int lane   = tid & 31;
    const int wid    = tid >> 5;
    const int warp_m = wid & 1;
    const int warp_n = wid >> 1;
    const int brow   = blockIdx.y * TBM;
    const int bcol   = blockIdx.x * TBN;

    const int lq = lane >> 2;
    const int lr = lane & 3;

    // staging indices: A tile = 512 float4 (2/thread), B tile = 512 float4
    const int rA0 = tid >> 2,         cA0 = tid & 3;
    const int rA1 = (tid + 256) >> 2, cA1 = (tid + 256) & 3;
    const int rB0 = tid >> 5,         cB0 = tid & 31;
    const int rB1 = (tid + 256) >> 5, cB1 = (tid + 256) & 31;

    const uint32_t sA = (uint32_t)__cvta_generic_to_shared(&As[0][0]);
    const uint32_t sB = (uint32_t)__cvta_generic_to_shared(&Bs[0][0]);
    const uint32_t aStage = TBM * AST * 4;   // bytes per A stage
    const uint32_t bStage = TBK * BST * 4;   // bytes per B stage

    float acc[4][4][4];
    #pragma unroll
    for (int mt = 0; mt < 4; mt++)
        #pragma unroll
        for (int nt = 0; nt < 4; nt++)
            #pragma unroll
            for (int i = 0; i < 4; i++) acc[mt][nt][i] = 0.f;

    const int NT = K / TBK;

    // prologue: stage 0
    cp16(sA + (rA0 * AST + cA0 * 4) * 4, A + (size_t)(brow + rA0) * K + cA0 * 4);
    cp16(sA + (rA1 * AST + cA1 * 4) * 4, A + (size_t)(brow + rA1) * K + cA1 * 4);
    cp16(sB + (rB0 * BST + cB0 * 4) * 4, B + (size_t)rB0 * N + bcol + cB0 * 4);
    cp16(sB + (rB1 * BST + cB1 * 4) * 4, B + (size_t)rB1 * N + bcol + cB1 * 4);
    cp_commit();

    for (int t = 0; t < NT; t++) {
        if (t + 1 < NT) {
            const int st = (t + 1) & 1;
            const int k0 = (t + 1) * TBK;
            const uint32_t sAs = sA + st * aStage;
            const uint32_t sBs = sB + st * bStage;
            cp16(sAs + (rA0 * AST + cA0 * 4) * 4, A + (size_t)(brow + rA0) * K + k0 + cA0 * 4);
            cp16(sAs + (rA1 * AST + cA1 * 4) * 4, A + (size_t)(brow + rA1) * K + k0 + cA1 * 4);
            cp16(sBs + (rB0 * BST + cB0 * 4) * 4, B + (size_t)(k0 + rB0) * N + bcol + cB0 * 4);
            cp16(sBs + (rB1 * BST + cB1 * 4) * 4, B + (size_t)(k0 + rB1) * N + bcol + cB1 * 4);
            cp_commit();
            cp_wait1();
        } else {
            cp_wait0();
        }
        __syncthreads();

        const float* Ac = &As[t & 1][0];
        const float* Bc = &Bs[t & 1][0];
        #pragma unroll
        for (int ks = 0; ks < 2; ks++) {
            const int kk = ks * 8;
            uint32_t a[4][4], b[4][2];
            #pragma unroll
            for (int mt = 0; mt < 4; mt++) {
                const int r = warp_m * 64 + mt * 16 + lq;
                a[mt][0] = f2tf32(Ac[r * AST + kk + lr]);
                a[mt][1] = f2tf32(Ac[(r + 8) * AST + kk + lr]);
                a[mt][2] = f2tf32(Ac[r * AST + kk + lr + 4]);
                a[mt][3] = f2tf32(Ac[(r + 8) * AST + kk + lr + 4]);
            }
            #pragma unroll
            for (int nt = 0; nt < 4; nt++) {
                const int n = warp_n * 32 + nt * 8 + lq;
                b[nt][0] = f2tf32(Bc[(kk + lr) * BST + n]);
                b[nt][1] = f2tf32(Bc[(kk + lr + 4) * BST + n]);
            }
            #pragma unroll
            for (int mt = 0; mt < 4; mt++)
                #pragma unroll
                for (int nt = 0; nt < 4; nt++)
                    mma_tf32(acc[mt][nt], a[mt], b[nt]);
        }
        __syncthreads();
    }

    // ---- epilogue (R12's, unchanged)
    if (V_TRANS && bcol >= 2 * CDIM) {
        #pragma unroll
        for (int mt = 0; mt < 4; mt++) {
            const int rowg = brow + warp_m * 64 + mt * 16 + lq;
            const int bb = rowg >> 11;
            const int t0 = rowg & (SEQ - 1);
            #pragma unroll
            for (int nt = 0; nt < 4; nt++) {
                const int col = (bcol - 2 * CDIM) + warp_n * 32 + nt * 8 + 2 * lr;
                const int h = col >> 6;
                const int d = col & 63;
                float* base = g_vt + ((size_t)(bb * NHEAD + h) * HDIM + d) * SEQ;
                base[t0]           = acc[mt][nt][0];
                base[SEQ + t0]     = acc[mt][nt][1];
                base[t0 + 8]       = acc[mt][nt][2];
                base[SEQ + t0 + 8] = acc[mt][nt][3];
            }
        }
    } else {
        #pragma unroll
        for (int mt = 0; mt < 4; mt++) {
            const int row0 = brow + warp_m * 64 + mt * 16 + lq;
            #pragma unroll
            for (int nt = 0; nt < 4; nt++) {
                const int col = bcol + warp_n * 32 + nt * 8 + 2 * lr;
                *(float2*)(C + (size_t)row0 * N + col) =
                    make_float2(acc[mt][nt][0], acc[mt][nt][1]);
                *(float2*)(C + (size_t)(row0 + 8) * N + col) =
                    make_float2(acc[mt][nt][2], acc[mt][nt][3]);
            }
        }
    }
}

__global__ __launch_bounds__(256) void qkv_gemm_kernel(
    const float* __restrict__ x, const float* __restrict__ Wqkv)
{
    tgemm_body<true>(x, Wqkv, g_qkv, N_QKV, CDIM);
}

__global__ __launch_bounds__(256) void proj_gemm_kernel(
    const float* __restrict__ Wproj, float* __restrict__ out)
{
    tgemm_body<false>(g_y, Wproj, out, CDIM, CDIM);
}

// ---------------------------------------------------------------------------
// Attention kernel — R12's, byte-for-byte unchanged (passed twice).
// QK^T tf32 m16n8k8; PV fp16 m16n8k16 with V^T from g_vt.
// grid = (SEQ/128, NHEAD, BATCH), 256 threads.
// ---------------------------------------------------------------------------
#define FA_Q 128
#define FA_K 64
#define FA_ST 72
#define FA_VST 36

__global__ __launch_bounds__(256) void flash_attn_tc_kernel()
{
    __shared__ uint32_t KVs[2 * FA_K * FA_ST];          // 36.9 KB
    uint32_t* Ks   = KVs;
    uint32_t* VsTu = KVs + FA_K * FA_ST;

    const float* __restrict__ qkv = g_qkv;
    const float* __restrict__ vt  = g_vt;
    float* __restrict__ y = g_y;

    const int tid  = threadIdx.x;
    const int lane = tid & 31;
    const int w    = tid >> 5;
    const int lq   = lane >> 2;
    const int lr   = lane & 3;
    const int h    = blockIdx.y;
    const int b    = blockIdx.z;
    const int q0   = blockIdx.x * FA_Q;
    const size_t rowbase = (size_t)b * SEQ;
    const float scale = 0.125f;

    #pragma unroll
    for (int i = 0; i < 8; i++) {
        int idx = tid + i * 256;
        int r  = idx >> 4;
        int c4 = idx & 15;
        float4 v = *(const float4*)(qkv + (rowbase + q0 + r) * N_QKV + h * HDIM + c4 * 4);
        uint4 t;
        t.x = f2tf32(v.x); t.y = f2tf32(v.y);
        t.z = f2tf32(v.z); t.w = f2tf32(v.w);
        *(uint4*)&KVs[r * FA_ST + c4 * 4] = t;
    }
    __syncthreads();

    uint32_t qf[8][4];
    {
        const int r0 = (w * 16 + lq) * FA_ST;
        const int r1 = (w * 16 + lq + 8) * FA_ST;
        #pragma unroll
        for (int ks = 0; ks < 8; ks++) {
            const int kk = ks * 8;
            qf[ks][0] = KVs[r0 + kk + lr];
            qf[ks][1] = KVs[r1 + kk + lr];
            qf[ks][2] = KVs[r0 + kk + lr + 4];
            qf[ks][3] = KVs[r1 + kk + lr + 4];
        }
    }

    float o[8][4];
    #pragma unroll
    for (int nt = 0; nt < 8; nt++)
        #pragma unroll
        for (int i = 0; i < 4; i++) o[nt][i] = 0.f;
    float m0 = -INFINITY, m1 = -INFINITY, l0 = 0.f, l1 = 0.f;

    const int row0 = q0 + w * 16 + lq;
    const int row1 = row0 + 8;
    const int wrow_max = q0 + w * 16 + 15;
    const int ntiles = 2 * blockIdx.x + 2;

    for (int t = 0; t < ntiles; t++) {
        const int krow0 = t * FA_K;
        __syncthreads();
        #pragma unroll
        for (int i = 0; i < 4; i++) {
            int idx = tid + i * 256;
            int r  = idx >> 4;
            int c4 = idx & 15;
            const float* base = qkv + (rowbase + krow0 + r) * N_QKV + CDIM + h * HDIM;
            float4 kv = *(const float4*)(base + c4 * 4);
            uint4 tk;
            tk.x = f2tf32(kv.x); tk.y = f2tf32(kv.y);
            tk.z = f2tf32(kv.z); tk.w = f2tf32(kv.w);
            *(uint4*)&Ks[r * FA_ST + c4 * 4] = tk;
        }
        #pragma unroll
        for (int i = 0; i < 4; i++) {
            int idx = tid + i * 256;
            int r  = idx >> 4;
            int c4 = idx & 15;
            const float* base = vt + ((size_t)(b * NHEAD + h) * HDIM + r) * SEQ + krow0;
            float4 vv = *(const float4*)(base + c4 * 4);
            VsTu[r * FA_VST + c4 * 2]     = h2u(vv.x, vv.y);
            VsTu[r * FA_VST + c4 * 2 + 1] = h2u(vv.z, vv.w);
        }
        __syncthreads();

        if (krow0 > wrow_max) continue;

        float s[8][4];
        #pragma unroll
        for (int nt = 0; nt < 8; nt++)
            #pragma unroll
            for (int i = 0; i < 4; i++) s[nt][i] = 0.f;

        #pragma unroll
        for (int ks = 0; ks < 8; ks++) {
            const int kk = ks * 8;
            #pragma unroll
            for (int nt = 0; nt < 8; nt++) {
                uint32_t bb[2];
                bb[0] = Ks[(nt * 8 + lq) * FA_ST + kk + lr];
                bb[1] = Ks[(nt * 8 + lq) * FA_ST + kk + lr + 4];
                mma_tf32(s[nt], qf[ks], bb);
            }
        }

        const bool diag = (krow0 + FA_K - 1 > q0 + w * 16);
        #pragma unroll
        for (int nt = 0; nt < 8; nt++) {
            const int col = krow0 + nt * 8 + 2 * lr;
            s[nt][0] = (diag && col     > row0) ? -INFINITY : s[nt][0] * scale;
            s[nt][1] = (diag && col + 1 > row0) ? -INFINITY : s[nt][1] * scale;
            s[nt][2] = (diag && col     > row1) ? -INFINITY : s[nt][2] * scale;
            s[nt][3] = (diag && col + 1 > row1) ? -INFINITY : s[nt][3] * scale;
        }

        float mx0 = -INFINITY, mx1 = -INFINITY;
        #pragma unroll
        for (int nt = 0; nt < 8; nt++) {
            mx0 = fmaxf(mx0, fmaxf(s[nt][0], s[nt][1]));
            mx1 = fmaxf(mx1, fmaxf(s[nt][2], s[nt][3]));
        }
        mx0 = fmaxf(mx0, __shfl_xor_sync(0xffffffffu, mx0, 1));
        mx0 = fmaxf(mx0, __shfl_xor_sync(0xffffffffu, mx0, 2));
        mx1 = fmaxf(mx1, __shfl_xor_sync(0xffffffffu, mx1, 1));
        mx1 = fmaxf(mx1, __shfl_xor_sync(0xffffffffu, mx1, 2));

        const float mn0 = fmaxf(m0, mx0);
        const float mn1 = fmaxf(m1, mx1);
        const float cr0 = __expf(m0 - mn0);
        const float cr1 = __expf(m1 - mn1);
        m0 = mn0; m1 = mn1;

        float sum0 = 0.f, sum1 = 0.f;
        #pragma unroll
        for (int nt = 0; nt < 8; nt++) {
            s[nt][0] = __expf(s[nt][0] - mn0); sum0 += s[nt][0];
            s[nt][1] = __expf(s[nt][1] - mn0); sum0 += s[nt][1];
            s[nt][2] = __expf(s[nt][2] - mn1); sum1 += s[nt][2];
            s[nt][3] = __expf(s[nt][3] - mn1); sum1 += s[nt][3];
        }
        sum0 += __shfl_xor_sync(0xffffffffu, sum0, 1);
        sum0 += __shfl_xor_sync(0xffffffffu, sum0, 2);
        sum1 += __shfl_xor_sync(0xffffffffu, sum1, 1);
        sum1 += __shfl_xor_sync(0xffffffffu, sum1, 2);
        l0 = l0 * cr0 + sum0;
        l1 = l1 * cr1 + sum1;

        #pragma unroll
        for (int nt = 0; nt < 8; nt++) {
            o[nt][0] *= cr0; o[nt][1] *= cr0;
            o[nt][2] *= cr1; o[nt][3] *= cr1;
        }

        #pragma unroll
        for (int ksv = 0; ksv < 4; ksv++) {
            uint32_t a[4];
            a[0] = h2u(s[2*ksv][0],     s[2*ksv][1]);
            a[1] = h2u(s[2*ksv][2],     s[2*ksv][3]);
            a[2] = h2u(s[2*ksv + 1][0], s[2*ksv + 1][1]);
            a[3] = h2u(s[2*ksv + 1][2], s[2*ksv + 1][3]);
            #pragma unroll
            for (int nt = 0; nt < 8; nt++) {
                const int base = (nt * 8 + lq) * FA_VST + 8 * ksv + lr;
                mma_f16(o[nt], a, VsTu[base], VsTu[base + 4]);
            }
        }
    }

    const float inv0 = 1.f / l0;
    const float inv1 = 1.f / l1;
    #pragma unroll
    for (int nt = 0; nt < 8; nt++) {
        const int col = h * HDIM + nt * 8 + 2 * lr;
        *(float2*)(y + (rowbase + row0) * CDIM + col) =
            make_float2(o[nt][0] * inv0, o[nt][1] * inv0);
        *(float2*)(y + (rowbase + row1) * CDIM + col) =
            make_float2(o[nt][2] * inv1, o[nt][3] * inv1);
    }
}

// ---------------------------------------------------------------------------
// Launch — pure kernel launches, 3 kernels, 1D blocks only.
// ---------------------------------------------------------------------------
extern "C" void kernel_launch(void* const* d_in, const int* in_sizes, int n_in,
                              void* d_out, int out_size)
{
    const float* x     = (const float*)d_in[0];   // [B,T,C]
    const float* Wqkv  = (const float*)d_in[1];   // [C,3C]
    const float* Wproj = (const float*)d_in[2];   // [C,C]
    float* out = (float*)d_out;                   // [B,T,C]

    {   // 1) qkv = x @ Wqkv (q|k float -> g_qkv, V^T float -> g_vt)
        dim3 grid(N_QKV / TBN, MROWS / TBM);
        qkv_gemm_kernel<<<grid, 256>>>(x, Wqkv);
    }
    {   // 2) fused causal attention -> g_y (float)
        dim3 grid(SEQ / FA_Q, NHEAD, BATCH);
        flash_attn_tc_kernel<<<grid, 256>>>();
    }
    {   // 3) out = y @ Wproj (fp32 out)
        dim3 grid(CDIM / TBN, MROWS / TBM);
        proj_gemm_kernel<<<grid, 256>>>(Wproj, out);
    }
}

// round 15
// speedup vs baseline: 1.3004x; 1.3004x over previous
#include <cuda_runtime.h>
#include <cuda_bf16.h>
#include <cuda_fp16.h>
#include <stdint.h>
#include <math.h>

// Problem constants
#define BATCH 2
#define SEQ   2048
#define CDIM  1024
#define NHEAD 16
#define HDIM  64
#define MROWS (BATCH*SEQ)        // 4096
#define N_QKV (3*CDIM)           // 3072

// Scratch (device globals — allocation-free). Float only (proven safe set).
__device__ float g_qkv[(size_t)MROWS * N_QKV];              // q|k float (V region unused)
__device__ float g_vt[(size_t)BATCH * NHEAD * HDIM * SEQ];  // V^T float [B,NH,HD,T]
__device__ float g_y[(size_t)MROWS * CDIM];                 // attention out [B*T, C]

// ---------------------------------------------------------------------------
// helpers (R12's exactly)
// ---------------------------------------------------------------------------
__device__ __forceinline__ uint32_t h2u(float lo, float hi) {
    __half2 h = __floats2half2_rn(lo, hi);
    return *(uint32_t*)&h;
}

__device__ __forceinline__ void mma_f16(float* c, const uint32_t* a, uint32_t b0, uint32_t b1) {
    asm volatile("mma.sync.aligned.m16n8k16.row.col.f32.f16.f16.f32 "
        "{%0,%1,%2,%3}, {%4,%5,%6,%7}, {%8,%9}, {%0,%1,%2,%3};"
        : "+f"(c[0]), "+f"(c[1]), "+f"(c[2]), "+f"(c[3])
        : "r"(a[0]), "r"(a[1]), "r"(a[2]), "r"(a[3]), "r"(b0), "r"(b1));
}

// ---------------------------------------------------------------------------
// FP16 tensor-core GEMM — R12's passing version, byte-for-byte.
// C = A[M,K] @ B[K,N], fp32 in gmem, converted to half2 during staging.
// 128x128x32 block tile, 256 threads (8 warps 2x4), warp tile 64x32.
// ---------------------------------------------------------------------------
#define TBM 128
#define TBN 128
#define TBK 32
#define GST 20   // half2-word row stride; banks 20*lq+lr all-distinct

template <bool V_TRANS>
__device__ __forceinline__ void tgemm_body(
    const float* __restrict__ A, const float* __restrict__ B,
    float* __restrict__ C, int N, int K)
{
    __shared__ uint32_t As[TBM * GST];   // 10.2 KB
    __shared__ uint32_t Bs[TBN * GST];   // 10.2 KB

    const int tid    = threadIdx.x;
    const int lane   = tid & 31;
    const int wid    = tid >> 5;
    const int warp_m = wid & 1;
    const int warp_n = wid >> 1;
    const int brow   = blockIdx.y * TBM;
    const int bcol   = blockIdx.x * TBN;

    const int lq = lane >> 2;
    const int lr = lane & 3;

    float acc[4][4][4];
    #pragma unroll
    for (int mt = 0; mt < 4; mt++)
        #pragma unroll
        for (int nt = 0; nt < 4; nt++)
            #pragma unroll
            for (int i = 0; i < 4; i++) acc[mt][nt][i] = 0.f;

    for (int k0 = 0; k0 < K; k0 += TBK) {
        // ---- stage A: 128 rows x 32 floats -> half2 k-pairs; 4 slots/thread
        #pragma unroll
        for (int i = 0; i < 4; i++) {
            int idx = tid + i * 256;
            int r  = idx >> 3;          // 0..127
            int c4 = idx & 7;           // 0..7
            float4 v = *(const float4*)(A + (size_t)(brow + r) * K + k0 + c4 * 4);
            uint2 t; t.x = h2u(v.x, v.y); t.y = h2u(v.z, v.w);
            *(uint2*)(&As[r * GST + c4 * 2]) = t;
        }
        // ---- stage B: 32 k-rows x 128 cols -> [n][k2] k-pairs; 2 slots/thread
        #pragma unroll
        for (int i = 0; i < 2; i++) {
            int idx = tid + i * 256;    // 0..511
            int p   = idx & 15;         // k-pair 0..15
            int c4g = idx >> 4;         // col group 0..31
            const float* b0p = B + (size_t)(k0 + 2 * p) * N + bcol + c4g * 4;
            float4 r0 = *(const float4*)(b0p);
            float4 r1 = *(const float4*)(b0p + N);
            Bs[(c4g * 4 + 0) * GST + p] = h2u(r0.x, r1.x);
            Bs[(c4g * 4 + 1) * GST + p] = h2u(r0.y, r1.y);
            Bs[(c4g * 4 + 2) * GST + p] = h2u(r0.z, r1.z);
            Bs[(c4g * 4 + 3) * GST + p] = h2u(r0.w, r1.w);
        }
        __syncthreads();

        #pragma unroll
        for (int ks = 0; ks < TBK / 16; ks++) {
            const int kk = ks * 8;
            uint32_t a[4][4], b[4][2];
            #pragma unroll
            for (int mt = 0; mt < 4; mt++) {
                const int r = warp_m * 64 + mt * 16 + lq;
                a[mt][0] = As[r * GST + kk + lr];
                a[mt][1] = As[(r + 8) * GST + kk + lr];
                a[mt][2] = As[r * GST + kk + lr + 4];
                a[mt][3] = As[(r + 8) * GST + kk + lr + 4];
            }
            #pragma unroll
            for (int nt = 0; nt < 4; nt++) {
                const int n = warp_n * 32 + nt * 8 + lq;
                b[nt][0] = Bs[n * GST + kk + lr];
                b[nt][1] = Bs[n * GST + kk + lr + 4];
            }
            #pragma unroll
            for (int mt = 0; mt < 4; mt++)
                #pragma unroll
                for (int nt = 0; nt < 4; nt++)
                    mma_f16(acc[mt][nt], a[mt], b[nt][0], b[nt][1]);
        }
        __syncthreads();
    }

    // ---- epilogue
    if (V_TRANS && bcol >= 2 * CDIM) {
        #pragma unroll
        for (int mt = 0; mt < 4; mt++) {
            const int rowg = brow + warp_m * 64 + mt * 16 + lq;
            const int bb = rowg >> 11;
            const int t0 = rowg & (SEQ - 1);
            #pragma unroll
            for (int nt = 0; nt < 4; nt++) {
                const int col = (bcol - 2 * CDIM) + warp_n * 32 + nt * 8 + 2 * lr;
                const int h = col >> 6;
                const int d = col & 63;
                float* base = g_vt + ((size_t)(bb * NHEAD + h) * HDIM + d) * SEQ;
                base[t0]           = acc[mt][nt][0];
                base[SEQ + t0]     = acc[mt][nt][1];
                base[t0 + 8]       = acc[mt][nt][2];
                base[SEQ + t0 + 8] = acc[mt][nt][3];
            }
        }
    } else {
        #pragma unroll
        for (int mt = 0; mt < 4; mt++) {
            const int row0 = brow + warp_m * 64 + mt * 16 + lq;
            #pragma unroll
            for (int nt = 0; nt < 4; nt++) {
                const int col = bcol + warp_n * 32 + nt * 8 + 2 * lr;
                *(float2*)(C + (size_t)row0 * N + col) =
                    make_float2(acc[mt][nt][0], acc[mt][nt][1]);
                *(float2*)(C + (size_t)(row0 + 8) * N + col) =
                    make_float2(acc[mt][nt][2], acc[mt][nt][3]);
            }
        }
    }
}

__global__ __launch_bounds__(256) void qkv_gemm_kernel(
    const float* __restrict__ x, const float* __restrict__ Wqkv)
{
    tgemm_body<true>(x, Wqkv, g_qkv, N_QKV, CDIM);
}

__global__ __launch_bounds__(256) void proj_gemm_kernel(
    const float* __restrict__ Wproj, float* __restrict__ out)
{
    tgemm_body<false>(g_y, Wproj, out, CDIM, CDIM);
}

// ---------------------------------------------------------------------------
// Fused causal flash attention — ALL fp16 m16n8k16 (QK^T and PV).
// Q/K staged as half2 words [row][k2] stride 36 (conflict-free); V^T as in
// R12. Softmax/mask/epilogue identical to the twice-passed R12 version.
// grid = (SEQ/128, NHEAD, BATCH), 256 threads (8 warps x 16 query rows).
// ---------------------------------------------------------------------------
#define FA_Q 128
#define FA_K 64
#define FA_HST 36    // half2-word row stride for Q/K/V tiles

__global__ __launch_bounds__(256) void flash_attn_tc_kernel()
{
    // Q staging (128*36 words, 18.4 KB) reused as { K 64*36 | V^T 64*36 }
    __shared__ uint32_t KVs[128 * FA_HST];
    uint32_t* Ks   = KVs;
    uint32_t* VsTu = KVs + FA_K * FA_HST;

    const float* __restrict__ qkv = g_qkv;
    const float* __restrict__ vt  = g_vt;
    float* __restrict__ y = g_y;

    const int tid  = threadIdx.x;
    const int lane = tid & 31;
    const int w    = tid >> 5;
    const int lq   = lane >> 2;
    const int lr   = lane & 3;
    const int h    = blockIdx.y;
    const int b    = blockIdx.z;
    const int q0   = blockIdx.x * FA_Q;
    const size_t rowbase = (size_t)b * SEQ;
    const float scale = 0.125f;

    // ---- stage Q (128 x 64 floats -> half2 words), 8 float4 per thread
    #pragma unroll
    for (int i = 0; i < 8; i++) {
        int idx = tid + i * 256;
        int r  = idx >> 4;               // 0..127
        int c4 = idx & 15;               // 0..15
        float4 v = *(const float4*)(qkv + (rowbase + q0 + r) * N_QKV + h * HDIM + c4 * 4);
        uint2 t; t.x = h2u(v.x, v.y); t.y = h2u(v.z, v.w);
        *(uint2*)&KVs[r * FA_HST + c4 * 2] = t;
    }
    __syncthreads();

    uint32_t qf[4][4];                   // fp16 A-frags, full HD=64 (4 k16 steps)
    {
        const int r0 = (w * 16 + lq) * FA_HST;
        const int r1 = (w * 16 + lq + 8) * FA_HST;
        #pragma unroll
        for (int ks = 0; ks < 4; ks++) {
            const int kk = ks * 8;
            qf[ks][0] = KVs[r0 + kk + lr];
            qf[ks][1] = KVs[r1 + kk + lr];
            qf[ks][2] = KVs[r0 + kk + lr + 4];
            qf[ks][3] = KVs[r1 + kk + lr + 4];
        }
    }

    float o[8][4];
    #pragma unroll
    for (int nt = 0; nt < 8; nt++)
        #pragma unroll
        for (int i = 0; i < 4; i++) o[nt][i] = 0.f;
    float m0 = -INFINITY, m1 = -INFINITY, l0 = 0.f, l1 = 0.f;

    const int row0 = q0 + w * 16 + lq;
    const int row1 = row0 + 8;
    const int wrow_max = q0 + w * 16 + 15;
    const int ntiles = 2 * blockIdx.x + 2;

    for (int t = 0; t < ntiles; t++) {
        const int krow0 = t * FA_K;
        __syncthreads();
        // ---- K tile: 64 keys x 64 floats -> half2 [key][k2]; 4 float4/thread
        #pragma unroll
        for (int i = 0; i < 4; i++) {
            int idx = tid + i * 256;
            int r  = idx >> 4;           // 0..63
            int c4 = idx & 15;
            const float* base = qkv + (rowbase + krow0 + r) * N_QKV + CDIM + h * HDIM;
            float4 kv = *(const float4*)(base + c4 * 4);
            uint2 tk; tk.x = h2u(kv.x, kv.y); tk.y = h2u(kv.z, kv.w);
            *(uint2*)&Ks[r * FA_HST + c4 * 2] = tk;
        }
        // ---- V^T tile: 64 hd x 64 keys -> half2 [hd][key2]; 4 float4/thread
        #pragma unroll
        for (int i = 0; i < 4; i++) {
            int idx = tid + i * 256;
            int r  = idx >> 4;           // 0..63
            int c4 = idx & 15;
            const float* base = vt + ((size_t)(b * NHEAD + h) * HDIM + r) * SEQ + krow0;
            float4 vv = *(const float4*)(base + c4 * 4);
            uint2 tv; tv.x = h2u(vv.x, vv.y); tv.y = h2u(vv.z, vv.w);
            *(uint2*)&VsTu[r * FA_HST + c4 * 2] = tv;
        }
        __syncthreads();

        if (krow0 > wrow_max) continue;

        // ---- S = Q K^T (fp16 k16, 4 k-steps x 8 n-tiles)
        float s[8][4];
        #pragma unroll
        for (int nt = 0; nt < 8; nt++)
            #pragma unroll
            for (int i = 0; i < 4; i++) s[nt][i] = 0.f;

        #pragma unroll
        for (int ks = 0; ks < 4; ks++) {
            const int kk = ks * 8;
            #pragma unroll
            for (int nt = 0; nt < 8; nt++) {
                const int base = (nt * 8 + lq) * FA_HST + kk + lr;
                mma_f16(s[nt], qf[ks], Ks[base], Ks[base + 4]);
            }
        }

        const bool diag = (krow0 + FA_K - 1 > q0 + w * 16);
        #pragma unroll
        for (int nt = 0; nt < 8; nt++) {
            const int col = krow0 + nt * 8 + 2 * lr;
            s[nt][0] = (diag && col     > row0) ? -INFINITY : s[nt][0] * scale;
            s[nt][1] = (diag && col + 1 > row0) ? -INFINITY : s[nt][1] * scale;
            s[nt][2] = (diag && col     > row1) ? -INFINITY : s[nt][2] * scale;
            s[nt][3] = (diag && col + 1 > row1) ? -INFINITY : s[nt][3] * scale;
        }

        // ---- online softmax (unchanged)
        float mx0 = -INFINITY, mx1 = -INFINITY;
        #pragma unroll
        for (int nt = 0; nt < 8; nt++) {
            mx0 = fmaxf(mx0, fmaxf(s[nt][0], s[nt][1]));
            mx1 = fmaxf(mx1, fmaxf(s[nt][2], s[nt][3]));
        }
        mx0 = fmaxf(mx0, __shfl_xor_sync(0xffffffffu, mx0, 1));
        mx0 = fmaxf(mx0, __shfl_xor_sync(0xffffffffu, mx0, 2));
        mx1 = fmaxf(mx1, __shfl_xor_sync(0xffffffffu, mx1, 1));
        mx1 = fmaxf(mx1, __shfl_xor_sync(0xffffffffu, mx1, 2));

        const float mn0 = fmaxf(m0, mx0);
        const float mn1 = fmaxf(m1, mx1);
        const float cr0 = __expf(m0 - mn0);
        const float cr1 = __expf(m1 - mn1);
        m0 = mn0; m1 = mn1;

        float sum0 = 0.f, sum1 = 0.f;
        #pragma unroll
        for (int nt = 0; nt < 8; nt++) {
            s[nt][0] = __expf(s[nt][0] - mn0); sum0 += s[nt][0];
            s[nt][1] = __expf(s[nt][1] - mn0); sum0 += s[nt][1];
            s[nt][2] = __expf(s[nt][2] - mn1); sum1 += s[nt][2];
            s[nt][3] = __expf(s[nt][3] - mn1); sum1 += s[nt][3];
        }
        sum0 += __shfl_xor_sync(0xffffffffu, sum0, 1);
        sum0 += __shfl_xor_sync(0xffffffffu, sum0, 2);
        sum1 += __shfl_xor_sync(0xffffffffu, sum1, 1);
        sum1 += __shfl_xor_sync(0xffffffffu, sum1, 2);
        l0 = l0 * cr0 + sum0;
        l1 = l1 * cr1 + sum1;

        #pragma unroll
        for (int nt = 0; nt < 8; nt++) {
            o[nt][0] *= cr0; o[nt][1] *= cr0;
            o[nt][2] *= cr1; o[nt][3] *= cr1;
        }

        // ---- O += P V (fp16): P C-frags pack straight into A-frags
        #pragma unroll
        for (int ksv = 0; ksv < 4; ksv++) {
            uint32_t a[4];
            a[0] = h2u(s[2*ksv][0],     s[2*ksv][1]);
            a[1] = h2u(s[2*ksv][2],     s[2*ksv][3]);
            a[2] = h2u(s[2*ksv + 1][0], s[2*ksv + 1][1]);
            a[3] = h2u(s[2*ksv + 1][2], s[2*ksv + 1][3]);
            #pragma unroll
            for (int nt = 0; nt < 8; nt++) {
                const int base = (nt * 8 + lq) * FA_HST + 8 * ksv + lr;
                mma_f16(o[nt], a, VsTu[base], VsTu[base + 4]);
            }
        }
    }

    const float inv0 = 1.f / l0;
    const float inv1 = 1.f / l1;
    #pragma unroll
    for (int nt = 0; nt < 8; nt++) {
        const int col = h * HDIM + nt * 8 + 2 * lr;
        *(float2*)(y + (rowbase + row0) * CDIM + col) =
            make_float2(o[nt][0] * inv0, o[nt][1] * inv0);
        *(float2*)(y + (rowbase + row1) * CDIM + col) =
            make_float2(o[nt][2] * inv1, o[nt][3] * inv1);
    }
}

// ---------------------------------------------------------------------------
// Launch — pure kernel launches, 3 kernels, 1D blocks only.
// ---------------------------------------------------------------------------
extern "C" void kernel_launch(void* const* d_in, const int* in_sizes, int n_in,
                              void* d_out, int out_size)
{
    const float* x     = (const float*)d_in[0];   // [B,T,C]
    const float* Wqkv  = (const float*)d_in[1];   // [C,3C]
    const float* Wproj = (const float*)d_in[2];   // [C,C]
    float* out = (float*)d_out;                   // [B,T,C]

    {   // 1) qkv = x @ Wqkv (q|k float -> g_qkv, V^T float -> g_vt)
        dim3 grid(N_QKV / TBN, MROWS / TBM);
        qkv_gemm_kernel<<<grid, 256>>>(x, Wqkv);
    }
    {   // 2) fused causal attention -> g_y (float)
        dim3 grid(SEQ / FA_Q, NHEAD, BATCH);
        flash_attn_tc_kernel<<<grid, 256>>>();
    }
    {   // 3) out = y @ Wproj (fp32 out)
        dim3 grid(CDIM / TBN, MROWS / TBM);
        proj_gemm_kernel<<<grid, 256>>>(Wproj, out);
    }
}

// round 17
// speedup vs baseline: 1.5828x; 1.2171x over previous
#include <cuda_runtime.h>
#include <cuda_bf16.h>
#include <cuda_fp16.h>
#include <stdint.h>
#include <math.h>

// Problem constants
#define BATCH 2
#define SEQ   2048
#define CDIM  1024
#define NHEAD 16
#define HDIM  64
#define MROWS (BATCH*SEQ)        // 4096
#define N_QKV (3*CDIM)           // 3072

// Scratch (device globals — allocation-free). Float only (proven safe set).
__device__ float g_qkv[(size_t)MROWS * N_QKV];              // q|k float (V region unused)
__device__ float g_vt[(size_t)BATCH * NHEAD * HDIM * SEQ];  // V^T float [B,NH,HD,T]
__device__ float g_y[(size_t)MROWS * CDIM];                 // attention out [B*T, C]

// ---------------------------------------------------------------------------
// helpers
// ---------------------------------------------------------------------------
__device__ __forceinline__ uint32_t h2u(float lo, float hi) {
    __half2 h = __floats2half2_rn(lo, hi);
    return *(uint32_t*)&h;
}

__device__ __forceinline__ uint32_t pack16(uint32_t lo, uint32_t hi) {
    return lo | (hi << 16);
}

__device__ __forceinline__ void mma_f16(float* c, const uint32_t* a, uint32_t b0, uint32_t b1) {
    asm volatile("mma.sync.aligned.m16n8k16.row.col.f32.f16.f16.f32 "
        "{%0,%1,%2,%3}, {%4,%5,%6,%7}, {%8,%9}, {%0,%1,%2,%3};"
        : "+f"(c[0]), "+f"(c[1]), "+f"(c[2]), "+f"(c[3])
        : "r"(a[0]), "r"(a[1]), "r"(a[2]), "r"(a[3]), "r"(b0), "r"(b1));
}

// ---------------------------------------------------------------------------
// FP16 tensor-core GEMM: C = A[M,K] @ B[K,N], fp32 in gmem, converted to
// half during staging. 128x128x32 block tile, 256 threads (8 warps 2x4),
// warp tile 64x32, m16n8k16, fp32 accumulate.
// As: [m][k2] half2 words, stride 20 (R12's proven conflict-free layout).
// Bs: [k][n] halves, stride 136 — COALESCED gmem loads (4 wf/warp-inst);
//     fragment k-pairs built from two adjacent rows via 16-bit LDS + pack.
//     Bank-verified: STS banks 68r+2c4 (phase-distinct); LDS banks
//     8*lr + n/2-word (<=2 lanes/word, broadcast).
// ---------------------------------------------------------------------------
#define TBM 128
#define TBN 128
#define TBK 32
#define GST 20    // As half2-word row stride
#define BSTH 136  // Bs half row stride

template <bool V_TRANS>
__device__ __forceinline__ void tgemm_body(
    const float* __restrict__ A, const float* __restrict__ B,
    float* __restrict__ C, int N, int K)
{
    __shared__ uint32_t As[TBM * GST];              // 10.2 KB
    __shared__ unsigned short Bsh[TBK * BSTH];      //  8.7 KB

    const int tid    = threadIdx.x;
    const int lane   = tid & 31;
    const int wid    = tid >> 5;
    const int warp_m = wid & 1;
    const int warp_n = wid >> 1;
    const int brow   = blockIdx.y * TBM;
    const int bcol   = blockIdx.x * TBN;

    const int lq = lane >> 2;
    const int lr = lane & 3;

    float acc[4][4][4];
    #pragma unroll
    for (int mt = 0; mt < 4; mt++)
        #pragma unroll
        for (int nt = 0; nt < 4; nt++)
            #pragma unroll
            for (int i = 0; i < 4; i++) acc[mt][nt][i] = 0.f;

    for (int k0 = 0; k0 < K; k0 += TBK) {
        // ---- stage A: 128 rows x 32 floats -> [m][k2] half2; 4 slots/thread
        #pragma unroll
        for (int i = 0; i < 4; i++) {
            int idx = tid + i * 256;
            int r  = idx >> 3;          // 0..127
            int c4 = idx & 7;           // 0..7
            float4 v = *(const float4*)(A + (size_t)(brow + r) * K + k0 + c4 * 4);
            uint2 t; t.x = h2u(v.x, v.y); t.y = h2u(v.z, v.w);
            *(uint2*)(&As[r * GST + c4 * 2]) = t;
        }
        // ---- stage B: 32 k-rows x 128 cols, COALESCED; -> [k][n] halves
        #pragma unroll
        for (int i = 0; i < 4; i++) {
            int idx = tid + i * 256;    // 0..1023
            int r  = idx >> 5;          // 0..31 (k row)
            int c4 = idx & 31;          // 0..31 (float4 col group)
            float4 v = *(const float4*)(B + (size_t)(k0 + r) * N + bcol + c4 * 4);
            uint2 t; t.x = h2u(v.x, v.y); t.y = h2u(v.z, v.w);
            *(uint2*)(&Bsh[r * BSTH + c4 * 4]) = t;
        }
        __syncthreads();

        #pragma unroll
        for (int ks = 0; ks < TBK / 16; ks++) {
            const int kk  = ks * 8;     // half2-word offset (A side)
            const int kkh = ks * 16;    // half offset (B side)
            uint32_t a[4][4], b[4][2];
            #pragma unroll
            for (int mt = 0; mt < 4; mt++) {
                const int r = warp_m * 64 + mt * 16 + lq;
                a[mt][0] = As[r * GST + kk + lr];
                a[mt][1] = As[(r + 8) * GST + kk + lr];
                a[mt][2] = As[r * GST + kk + lr + 4];
                a[mt][3] = As[(r + 8) * GST + kk + lr + 4];
            }
            #pragma unroll
            for (int nt = 0; nt < 4; nt++) {
                const int n = warp_n * 32 + nt * 8 + lq;
                const int kb = kkh + 2 * lr;
                b[nt][0] = pack16(Bsh[kb * BSTH + n],       Bsh[(kb + 1) * BSTH + n]);
                b[nt][1] = pack16(Bsh[(kb + 8) * BSTH + n], Bsh[(kb + 9) * BSTH + n]);
            }
            #pragma unroll
            for (int mt = 0; mt < 4; mt++)
                #pragma unroll
                for (int nt = 0; nt < 4; nt++)
                    mma_f16(acc[mt][nt], a[mt], b[nt][0], b[nt][1]);
        }
        __syncthreads();
    }

    // ---- epilogue (unchanged from R12/R15)
    if (V_TRANS && bcol >= 2 * CDIM) {
        #pragma unroll
        for (int mt = 0; mt < 4; mt++) {
            const int rowg = brow + warp_m * 64 + mt * 16 + lq;
            const int bb = rowg >> 11;
            const int t0 = rowg & (SEQ - 1);
            #pragma unroll
            for (int nt = 0; nt < 4; nt++) {
                const int col = (bcol - 2 * CDIM) + warp_n * 32 + nt * 8 + 2 * lr;
                const int h = col >> 6;
                const int d = col & 63;
                float* base = g_vt + ((size_t)(bb * NHEAD + h) * HDIM + d) * SEQ;
                base[t0]           = acc[mt][nt][0];
                base[SEQ + t0]     = acc[mt][nt][1];
                base[t0 + 8]       = acc[mt][nt][2];
                base[SEQ + t0 + 8] = acc[mt][nt][3];
            }
        }
    } else {
        #pragma unroll
        for (int mt = 0; mt < 4; mt++) {
            const int row0 = brow + warp_m * 64 + mt * 16 + lq;
            #pragma unroll
            for (int nt = 0; nt < 4; nt++) {
                const int col = bcol + warp_n * 32 + nt * 8 + 2 * lr;
                *(float2*)(C + (size_t)row0 * N + col) =
                    make_float2(acc[mt][nt][0], acc[mt][nt][1]);
                *(float2*)(C + (size_t)(row0 + 8) * N + col) =
                    make_float2(acc[mt][nt][2], acc[mt][nt][3]);
            }
        }
    }
}

__global__ __launch_bounds__(256) void qkv_gemm_kernel(
    const float* __restrict__ x, const float* __restrict__ Wqkv)
{
    tgemm_body<true>(x, Wqkv, g_qkv, N_QKV, CDIM);
}

__global__ __launch_bounds__(256) void proj_gemm_kernel(
    const float* __restrict__ Wproj, float* __restrict__ out)
{
    tgemm_body<false>(g_y, Wproj, out, CDIM, CDIM);
}

// ---------------------------------------------------------------------------
// Fused causal flash attention — R15's passing version, byte-for-byte.
// ALL fp16 m16n8k16 (QK^T and PV). grid = (SEQ/128, NHEAD, BATCH), 256 thr.
// ---------------------------------------------------------------------------
#define FA_Q 128
#define FA_K 64
#define FA_HST 36    // half2-word row stride for Q/K/V tiles

__global__ __launch_bounds__(256) void flash_attn_tc_kernel()
{
    __shared__ uint32_t KVs[128 * FA_HST];
    uint32_t* Ks   = KVs;
    uint32_t* VsTu = KVs + FA_K * FA_HST;

    const float* __restrict__ qkv = g_qkv;
    const float* __restrict__ vt  = g_vt;
    float* __restrict__ y = g_y;

    const int tid  = threadIdx.x;
    const int lane = tid & 31;
    const int w    = tid >> 5;
    const int lq   = lane >> 2;
    const int lr   = lane & 3;
    const int h    = blockIdx.y;
    const int b    = blockIdx.z;
    const int q0   = blockIdx.x * FA_Q;
    const size_t rowbase = (size_t)b * SEQ;
    const float scale = 0.125f;

    #pragma unroll
    for (int i = 0; i < 8; i++) {
        int idx = tid + i * 256;
        int r  = idx >> 4;
        int c4 = idx & 15;
        float4 v = *(const float4*)(qkv + (rowbase + q0 + r) * N_QKV + h * HDIM + c4 * 4);
        uint2 t; t.x = h2u(v.x, v.y); t.y = h2u(v.z, v.w);
        *(uint2*)&KVs[r * FA_HST + c4 * 2] = t;
    }
    __syncthreads();

    uint32_t qf[4][4];
    {
        const int r0 = (w * 16 + lq) * FA_HST;
        const int r1 = (w * 16 + lq + 8) * FA_HST;
        #pragma unroll
        for (int ks = 0; ks < 4; ks++) {
            const int kk = ks * 8;
            qf[ks][0] = KVs[r0 + kk + lr];
            qf[ks][1] = KVs[r1 + kk + lr];
            qf[ks][2] = KVs[r0 + kk + lr + 4];
            qf[ks][3] = KVs[r1 + kk + lr + 4];
        }
    }

    float o[8][4];
    #pragma unroll
    for (int nt = 0; nt < 8; nt++)
        #pragma unroll
        for (int i = 0; i < 4; i++) o[nt][i] = 0.f;
    float m0 = -INFINITY, m1 = -INFINITY, l0 = 0.f, l1 = 0.f;

    const int row0 = q0 + w * 16 + lq;
    const int row1 = row0 + 8;
    const int wrow_max = q0 + w * 16 + 15;
    const int ntiles = 2 * blockIdx.x + 2;

    for (int t = 0; t < ntiles; t++) {
        const int krow0 = t * FA_K;
        __syncthreads();
        #pragma unroll
        for (int i = 0; i < 4; i++) {
            int idx = tid + i * 256;
            int r  = idx >> 4;
            int c4 = idx & 15;
            const float* base = qkv + (rowbase + krow0 + r) * N_QKV + CDIM + h * HDIM;
            float4 kv = *(const float4*)(base + c4 * 4);
            uint2 tk; tk.x = h2u(kv.x, kv.y); tk.y = h2u(kv.z, kv.w);
            *(uint2*)&Ks[r * FA_HST + c4 * 2] = tk;
        }
        #pragma unroll
        for (int i = 0; i < 4; i++) {
            int idx = tid + i * 256;
            int r  = idx >> 4;
            int c4 = idx & 15;
            const float* base = vt + ((size_t)(b * NHEAD + h) * HDIM + r) * SEQ + krow0;
            float4 vv = *(const float4*)(base + c4 * 4);
            uint2 tv; tv.x = h2u(vv.x, vv.y); tv.y = h2u(vv.z, vv.w);
            *(uint2*)&VsTu[r * FA_HST + c4 * 2] = tv;
        }
        __syncthreads();

        if (krow0 > wrow_max) continue;

        float s[8][4];
        #pragma unroll
        for (int nt = 0; nt < 8; nt++)
            #pragma unroll
            for (int i = 0; i < 4; i++) s[nt][i] = 0.f;

        #pragma unroll
        for (int ks = 0; ks < 4; ks++) {
            const int kk = ks * 8;
            #pragma unroll
            for (int nt = 0; nt < 8; nt++) {
                const int base = (nt * 8 + lq) * FA_HST + kk + lr;
                mma_f16(s[nt], qf[ks], Ks[base], Ks[base + 4]);
            }
        }

        const bool diag = (krow0 + FA_K - 1 > q0 + w * 16);
        #pragma unroll
        for (int nt = 0; nt < 8; nt++) {
            const int col = krow0 + nt * 8 + 2 * lr;
            s[nt][0] = (diag && col     > row0) ? -INFINITY : s[nt][0] * scale;
            s[nt][1] = (diag && col + 1 > row0) ? -INFINITY : s[nt][1] * scale;
            s[nt][2] = (diag && col     > row1) ? -INFINITY : s[nt][2] * scale;
            s[nt][3] = (diag && col + 1 > row1) ? -INFINITY : s[nt][3] * scale;
        }

        float mx0 = -INFINITY, mx1 = -INFINITY;
        #pragma unroll
        for (int nt = 0; nt < 8; nt++) {
            mx0 = fmaxf(mx0, fmaxf(s[nt][0], s[nt][1]));
            mx1 = fmaxf(mx1, fmaxf(s[nt][2], s[nt][3]));
        }
        mx0 = fmaxf(mx0, __shfl_xor_sync(0xffffffffu, mx0, 1));
        mx0 = fmaxf(mx0, __shfl_xor_sync(0xffffffffu, mx0, 2));
        mx1 = fmaxf(mx1, __shfl_xor_sync(0xffffffffu, mx1, 1));
        mx1 = fmaxf(mx1, __shfl_xor_sync(0xffffffffu, mx1, 2));

        const float mn0 = fmaxf(m0, mx0);
        const float mn1 = fmaxf(m1, mx1);
        const float cr0 = __expf(m0 - mn0);
        const float cr1 = __expf(m1 - mn1);
        m0 = mn0; m1 = mn1;

        float sum0 = 0.f, sum1 = 0.f;
        #pragma unroll
        for (int nt = 0; nt < 8; nt++) {
            s[nt][0] = __expf(s[nt][0] - mn0); sum0 += s[nt][0];
            s[nt][1] = __expf(s[nt][1] - mn0); sum0 += s[nt][1];
            s[nt][2] = __expf(s[nt][2] - mn1); sum1 += s[nt][2];
            s[nt][3] = __expf(s[nt][3] - mn1); sum1 += s[nt][3];
        }
        sum0 += __shfl_xor_sync(0xffffffffu, sum0, 1);
        sum0 += __shfl_xor_sync(0xffffffffu, sum0, 2);
        sum1 += __shfl_xor_sync(0xffffffffu, sum1, 1);
        sum1 += __shfl_xor_sync(0xffffffffu, sum1, 2);
        l0 = l0 * cr0 + sum0;
        l1 = l1 * cr1 + sum1;

        #pragma unroll
        for (int nt = 0; nt < 8; nt++) {
            o[nt][0] *= cr0; o[nt][1] *= cr0;
            o[nt][2] *= cr1; o[nt][3] *= cr1;
        }

        #pragma unroll
        for (int ksv = 0; ksv < 4; ksv++) {
            uint32_t a[4];
            a[0] = h2u(s[2*ksv][0],     s[2*ksv][1]);
            a[1] = h2u(s[2*ksv][2],     s[2*ksv][3]);
            a[2] = h2u(s[2*ksv + 1][0], s[2*ksv + 1][1]);
            a[3] = h2u(s[2*ksv + 1][2], s[2*ksv + 1][3]);
            #pragma unroll
            for (int nt = 0; nt < 8; nt++) {
                const int base = (nt * 8 + lq) * FA_HST + 8 * ksv + lr;
                mma_f16(o[nt], a, VsTu[base], VsTu[base + 4]);
            }
        }
    }

    const float inv0 = 1.f / l0;
    const float inv1 = 1.f / l1;
    #pragma unroll
    for (int nt = 0; nt < 8; nt++) {
        const int col = h * HDIM + nt * 8 + 2 * lr;
        *(float2*)(y + (rowbase + row0) * CDIM + col) =
            make_float2(o[nt][0] * inv0, o[nt][1] * inv0);
        *(float2*)(y + (rowbase + row1) * CDIM + col) =
            make_float2(o[nt][2] * inv1, o[nt][3] * inv1);
    }
}

// ---------------------------------------------------------------------------
// Launch — pure kernel launches, 3 kernels, 1D blocks only.
// ---------------------------------------------------------------------------
extern "C" void kernel_launch(void* const* d_in, const int* in_sizes, int n_in,
                              void* d_out, int out_size)
{
    const float* x     = (const float*)d_in[0];   // [B,T,C]
    const float* Wqkv  = (const float*)d_in[1];   // [C,3C]
    const float* Wproj = (const float*)d_in[2];   // [C,C]
    float* out = (float*)d_out;                   // [B,T,C]

    {   // 1) qkv = x @ Wqkv (q|k float -> g_qkv, V^T float -> g_vt)
        dim3 grid(N_QKV / TBN, MROWS / TBM);
        qkv_gemm_kernel<<<grid, 256>>>(x, Wqkv);
    }
    {   // 2) fused causal attention -> g_y (float)
        dim3 grid(SEQ / FA_Q, NHEAD, BATCH);
        flash_attn_tc_kernel<<<grid, 256>>>();
    }
    {   // 3) out = y @ Wproj (fp32 out)
        dim3 grid(CDIM / TBN, MROWS / TBM);
        proj_gemm_kernel<<<grid, 256>>>(Wproj, out);
    }
}